// round 9
// baseline (speedup 1.0000x reference)
#include <cuda_runtime.h>
#include <cstdint>

#define T_TOK 2048
#define DDIM  2048
#define NOUT  11264
#define LEXP  16
#define HALF_B 5632

// ---------------- scratch (device globals: allocation-free) ----------------
__device__ __align__(16) float g_xr[(size_t)T_TOK * DDIM];   // tf32-rounded x
__device__ __align__(16) float g_wr[(size_t)NOUT * DDIM];    // tf32-rounded W
__device__ float g_xa[T_TOK * 32];                           // xa = x . A[l]
__device__ int   g_tok[T_TOK];                               // tokens sorted by expert
__device__ int   g_start[LEXP + 1];                          // expert segment starts

__device__ __forceinline__ float tf32_rn(float f) {
    uint32_t u;
    asm("cvt.rna.tf32.f32 %0, %1;" : "=r"(u) : "f"(f));
    return __uint_as_float(u);
}

// ---------------- kernel 1: bucket tokens by expert + zero xa ----------------
__global__ __launch_bounds__(1024) void sort_kernel(const void* idx_raw) {
    __shared__ int cnt[LEXP];
    __shared__ int base[LEXP];
    __shared__ int is64;
    int tid = threadIdx.x;
    if (tid < LEXP) cnt[tid] = 0;
    if (tid == 0) is64 = 1;
    __syncthreads();

    // sniff int32 vs int64: if int64 (values in [0,16)), every odd 32-bit word is 0
    const int* a32 = (const int*)idx_raw;
    for (int j = tid; j < 1024; j += blockDim.x)
        if (a32[2 * j + 1] != 0) is64 = 0;   // benign race
    __syncthreads();
    const long long* a64 = (const long long*)idx_raw;
    int use64 = is64;

    for (int t = tid; t < T_TOK; t += blockDim.x) {
        int l = use64 ? (int)a64[t] : a32[t];
        atomicAdd(&cnt[l], 1);
    }
    __syncthreads();
    if (tid == 0) {
        int s = 0;
        for (int l = 0; l < LEXP; ++l) { base[l] = s; g_start[l] = s; s += cnt[l]; }
        g_start[LEXP] = s;
    }
    __syncthreads();
    for (int t = tid; t < T_TOK; t += blockDim.x) {
        int l = use64 ? (int)a64[t] : a32[t];
        int p = atomicAdd(&base[l], 1);
        g_tok[p] = t;
    }
    for (int i = tid; i < T_TOK * 32; i += blockDim.x) g_xa[i] = 0.0f;
}

// ---------------- kernel 2: round x and W to tf32 (RN) ----------------
__global__ __launch_bounds__(256) void round_kernel(const float4* __restrict__ x,
                                                    const float4* __restrict__ W) {
    const size_t nx = (size_t)T_TOK * DDIM / 4;
    const size_t nw = (size_t)NOUT * DDIM / 4;
    float4* ox = (float4*)g_xr;
    float4* ow = (float4*)g_wr;
    size_t stride = (size_t)gridDim.x * blockDim.x;
    for (size_t i = (size_t)blockIdx.x * blockDim.x + threadIdx.x; i < nx + nw; i += stride) {
        float4 v;
        float4* dst;
        if (i < nx) { v = x[i]; dst = ox + i; }
        else        { v = W[i - nx]; dst = ow + (i - nx); }
        v.x = tf32_rn(v.x); v.y = tf32_rn(v.y);
        v.z = tf32_rn(v.z); v.w = tf32_rn(v.w);
        *dst = v;
    }
}

// ---------------- kernel 3: xa[t, j] = sum_d x[t,d] * A[l, d, j] ----------------
__global__ __launch_bounds__(512) void xa_kernel(const float* __restrict__ x,
                                                 const float* __restrict__ A) {
    __shared__ float As[128 * 32];
    int l = blockIdx.y;
    int d0 = blockIdx.x * 128;
    int tid = threadIdx.x;
    int lane = tid & 31, w = tid >> 5;

    size_t abase = ((size_t)l * DDIM + d0) * 32;
    for (int i = tid; i < 128 * 32; i += 512) As[i] = A[abase + i];
    __syncthreads();

    int pbeg = g_start[l], pend = g_start[l + 1];
    for (int p = pbeg + w; p < pend; p += 16) {
        int t = g_tok[p];
        float xv[4];
#pragma unroll
        for (int s = 0; s < 4; ++s)
            xv[s] = x[(size_t)t * DDIM + d0 + s * 32 + lane];
        float acc = 0.0f;
#pragma unroll
        for (int s = 0; s < 4; ++s) {
#pragma unroll
            for (int i = 0; i < 32; ++i) {
                float xb = __shfl_sync(0xffffffffu, xv[s], i);
                acc += xb * As[(s * 32 + i) * 32 + lane];
            }
        }
        atomicAdd(&g_xa[t * 32 + lane], acc);
    }
}

// ---------------- kernel 4: delta -> out (full init), B in regs, 8-way z-split
__global__ __launch_bounds__(256) void delta_kernel(const float* __restrict__ B,
                                                    float* __restrict__ out) {
    int l = blockIdx.y;
    int n0 = blockIdx.x * 512;
    int half = (n0 >= HALF_B) ? 1 : 0;
    int tid = threadIdx.x;
    int c0 = n0 + 2 * tid;

    int pbeg = g_start[l], pend = g_start[l + 1];
    int len = pend - pbeg;
    int per = (len + 7) >> 3;
    int s = pbeg + blockIdx.z * per;
    int e = s + per;
    if (e > pend) e = pend;
    if (s >= e) return;

    float2 Breg[16];
#pragma unroll
    for (int r = 0; r < 16; ++r)
        Breg[r] = *(const float2*)(B + ((size_t)l * 16 + r) * NOUT + c0);

    const float4* xa4base = (const float4*)(g_xa) + half * 4;

    for (int p = s; p < e; ++p) {
        int t = g_tok[p];
        float4 x0 = __ldg(xa4base + t * 8 + 0);
        float4 x1 = __ldg(xa4base + t * 8 + 1);
        float4 x2 = __ldg(xa4base + t * 8 + 2);
        float4 x3 = __ldg(xa4base + t * 8 + 3);
        float xs[16] = {x0.x, x0.y, x0.z, x0.w, x1.x, x1.y, x1.z, x1.w,
                        x2.x, x2.y, x2.z, x2.w, x3.x, x3.y, x3.z, x3.w};
        float2 acc = make_float2(0.0f, 0.0f);
#pragma unroll
        for (int r = 0; r < 16; ++r) {
            acc.x += xs[r] * Breg[r].x;
            acc.y += xs[r] * Breg[r].y;
        }
        *(float2*)(out + (size_t)t * NOUT + c0) = acc;
    }
}

// ---------------- kernel 5: main GEMM (tf32 mma.sync + ldmatrix) -------------
#define BM 128
#define BN 128
#define BK 32
#define PAD 36                          // 144 B row stride: LDSM rows hit 16r%128 -> conflict-free
#define STAGES 3
#define STAGE_FLOATS ((BM + BN) * PAD)  // 9216 floats
#define STAGE_BYTES (STAGE_FLOATS * 4)  // 36864 B
#define SMEM_GEMM (STAGES * STAGE_BYTES)

__device__ __forceinline__ void cpa16(uint32_t s, const void* g) {
    asm volatile("cp.async.cg.shared.global [%0], [%1], 16;\n" :: "r"(s), "l"(g));
}
__device__ __forceinline__ void ldsm4(uint32_t& r0, uint32_t& r1, uint32_t& r2,
                                      uint32_t& r3, uint32_t addr) {
    asm volatile("ldmatrix.sync.aligned.m8n8.x4.shared.b16 {%0,%1,%2,%3}, [%4];"
                 : "=r"(r0), "=r"(r1), "=r"(r2), "=r"(r3) : "r"(addr));
}

__global__ __launch_bounds__(256, 2) void gemm_kernel(float* __restrict__ out) {
    extern __shared__ float smem[];

    int tid = threadIdx.x;
    int lane = tid & 31;
    int warp = tid >> 5;
    int warpM = warp & 3;    // 4 warps in M  -> 32 rows each
    int warpN = warp >> 2;   // 2 warps in N  -> 64 cols each
    int grp = lane >> 2;     // 0..7
    int qid = lane & 3;      // 0..3

    int bm = blockIdx.x;     // 0..15
    int bn = blockIdx.y;     // 0..87

    const float* gA = g_xr + (size_t)(bm * BM) * DDIM;
    const float* gB = g_wr + (size_t)(bn * BN) * DDIM;

    int rbase = tid >> 3;    // 0..31
    int seg = tid & 7;       // 0..7

    uint32_t sBase = (uint32_t)__cvta_generic_to_shared(smem);

    // ldmatrix per-lane address offsets (bytes, relative to stage base).
    // A: matrix id = lane>>3; rows 0-7 / 8-15 select, col-block 16B select.
    uint32_t aOffL = (uint32_t)((warpM * 32 + (lane & 7) + ((lane >> 3) & 1) * 8) * PAD * 4
                                + (lane >> 4) * 16);
    // B: two n-tiles per x4: tile = 2j + (lane>>4), k-block = (lane>>3)&1.
    uint32_t bOffL = (uint32_t)(BM * PAD * 4
                                + (warpN * 64 + (lane >> 4) * 8 + (lane & 7)) * PAD * 4
                                + ((lane >> 3) & 1) * 16);

    float c[2][8][4];
#pragma unroll
    for (int mt = 0; mt < 2; ++mt)
#pragma unroll
        for (int nt = 0; nt < 8; ++nt)
#pragma unroll
            for (int i = 0; i < 4; ++i) c[mt][nt][i] = 0.0f;

    auto loadTiles = [&](int buf, int k0) {
        uint32_t aoff = sBase + (uint32_t)buf * STAGE_BYTES;
        uint32_t boff = aoff + (uint32_t)(BM * PAD) * 4u;
#pragma unroll
        for (int i = 0; i < 4; ++i) {
            int row = rbase + i * 32;
            cpa16(aoff + (uint32_t)(row * PAD + seg * 4) * 4u,
                  gA + (size_t)row * DDIM + k0 + seg * 4);
            cpa16(boff + (uint32_t)(row * PAD + seg * 4) * 4u,
                  gB + (size_t)row * DDIM + k0 + seg * 4);
        }
        asm volatile("cp.async.commit_group;\n");
    };

    auto compute = [&](uint32_t base) {   // base = sBase + buf*STAGE_BYTES
#pragma unroll
        for (int ks = 0; ks < 4; ++ks) {
            uint32_t a[2][4], b[8][2];
#pragma unroll
            for (int mt = 0; mt < 2; ++mt)
                ldsm4(a[mt][0], a[mt][1], a[mt][2], a[mt][3],
                      base + aOffL + (uint32_t)(mt * 16 * PAD * 4 + ks * 32));
#pragma unroll
            for (int j = 0; j < 4; ++j) {
                uint32_t r0, r1, r2, r3;
                ldsm4(r0, r1, r2, r3,
                      base + bOffL + (uint32_t)(j * 16 * PAD * 4 + ks * 32));
                b[2 * j][0] = r0; b[2 * j][1] = r1;
                b[2 * j + 1][0] = r2; b[2 * j + 1][1] = r3;
            }
#pragma unroll
            for (int mt = 0; mt < 2; ++mt) {
#pragma unroll
                for (int nt = 0; nt < 8; ++nt) {
                    asm volatile(
                        "mma.sync.aligned.m16n8k8.row.col.f32.tf32.tf32.f32 "
                        "{%0,%1,%2,%3}, {%4,%5,%6,%7}, {%8,%9}, {%0,%1,%2,%3};\n"
                        : "+f"(c[mt][nt][0]), "+f"(c[mt][nt][1]),
                          "+f"(c[mt][nt][2]), "+f"(c[mt][nt][3])
                        : "r"(a[mt][0]), "r"(a[mt][1]), "r"(a[mt][2]), "r"(a[mt][3]),
                          "r"(b[nt][0]), "r"(b[nt][1]));
                }
            }
        }
    };

    loadTiles(0, 0);
    loadTiles(1, BK);

    const int NITER = DDIM / BK;   // 64
#pragma unroll 1
    for (int it = 0; it < NITER - 4; it += 3) {
#pragma unroll
        for (int u = 0; u < 3; ++u) {
            asm volatile("cp.async.wait_group 1;\n");
            __syncthreads();
            loadTiles((u + 2) % STAGES, (it + u + 2) * BK);
            compute(sBase + (uint32_t)u * STAGE_BYTES);
        }
    }
    // tail: it = 60..63 (60 % 3 == 0)
#pragma unroll
    for (int u = 0; u < 4; ++u) {
        int it = 60 + u;
        if (it < NITER - 1) {
            asm volatile("cp.async.wait_group 1;\n");
        } else {
            asm volatile("cp.async.wait_group 0;\n");
        }
        __syncthreads();
        if (it + 2 < NITER)
            loadTiles((u + 2) % STAGES, (it + 2) * BK);
        compute(sBase + (uint32_t)((u % STAGES) * STAGE_BYTES));
    }

    // epilogue: out += acc (out already holds delta)
#pragma unroll
    for (int mt = 0; mt < 2; ++mt) {
#pragma unroll
        for (int nt = 0; nt < 8; ++nt) {
            int r = bm * BM + warpM * 32 + mt * 16 + grp;
            int col = bn * BN + warpN * 64 + nt * 8 + qid * 2;
            size_t o = (size_t)r * NOUT + col;
            float2* p0 = (float2*)(out + o);
            float2 v0 = *p0;
            v0.x += c[mt][nt][0];
            v0.y += c[mt][nt][1];
            *p0 = v0;
            float2* p1 = (float2*)(out + o + (size_t)8 * NOUT);
            float2 v1 = *p1;
            v1.x += c[mt][nt][2];
            v1.y += c[mt][nt][3];
            *p1 = v1;
        }
    }
}

// ---------------- launch ----------------
extern "C" void kernel_launch(void* const* d_in, const int* in_sizes, int n_in,
                              void* d_out, int out_size) {
    const float* x = (const float*)d_in[0];
    const float* W = (const float*)d_in[1];
    const float* A = (const float*)d_in[2];
    const float* B = (const float*)d_in[3];
    const void*  idx = d_in[4];
    float* out = (float*)d_out;

    (void)in_sizes; (void)n_in; (void)out_size;

    cudaFuncSetAttribute(gemm_kernel, cudaFuncAttributeMaxDynamicSharedMemorySize, SMEM_GEMM);

    sort_kernel<<<1, 1024>>>(idx);
    round_kernel<<<2048, 256>>>((const float4*)x, (const float4*)W);
    xa_kernel<<<dim3(16, 16), 512>>>(x, A);
    delta_kernel<<<dim3(22, 16, 8), 256>>>(B, out);
    gemm_kernel<<<dim3(16, 88), 256, SMEM_GEMM>>>(out);
}

// round 10
// speedup vs baseline: 1.3243x; 1.3243x over previous
#include <cuda_runtime.h>
#include <cuda_fp16.h>
#include <cstdint>

#define T_TOK 2048
#define DDIM  2048
#define NOUT  11264
#define LEXP  16
#define HALF_B 5632

// ---------------- scratch (device globals: allocation-free) ----------------
__device__ __align__(16) __half g_xh[(size_t)T_TOK * DDIM];  // fp16-rounded x
__device__ __align__(16) __half g_wh[(size_t)NOUT * DDIM];   // fp16-rounded W
__device__ float g_xa[T_TOK * 32];                           // xa = x . A[l]
__device__ int   g_tok[T_TOK];                               // tokens sorted by expert
__device__ int   g_start[LEXP + 1];                          // expert segment starts

// ---------------- kernel 1: bucket tokens by expert + zero xa ----------------
__global__ __launch_bounds__(1024) void sort_kernel(const void* idx_raw) {
    __shared__ int cnt[LEXP];
    __shared__ int base[LEXP];
    __shared__ int is64;
    int tid = threadIdx.x;
    if (tid < LEXP) cnt[tid] = 0;
    if (tid == 0) is64 = 1;
    __syncthreads();

    // sniff int32 vs int64: if int64 (values in [0,16)), every odd 32-bit word is 0
    const int* a32 = (const int*)idx_raw;
    for (int j = tid; j < 1024; j += blockDim.x)
        if (a32[2 * j + 1] != 0) is64 = 0;   // benign race
    __syncthreads();
    const long long* a64 = (const long long*)idx_raw;
    int use64 = is64;

    for (int t = tid; t < T_TOK; t += blockDim.x) {
        int l = use64 ? (int)a64[t] : a32[t];
        atomicAdd(&cnt[l], 1);
    }
    __syncthreads();
    if (tid == 0) {
        int s = 0;
        for (int l = 0; l < LEXP; ++l) { base[l] = s; g_start[l] = s; s += cnt[l]; }
        g_start[LEXP] = s;
    }
    __syncthreads();
    for (int t = tid; t < T_TOK; t += blockDim.x) {
        int l = use64 ? (int)a64[t] : a32[t];
        int p = atomicAdd(&base[l], 1);
        g_tok[p] = t;
    }
    for (int i = tid; i < T_TOK * 32; i += blockDim.x) g_xa[i] = 0.0f;
}

// ---------------- kernel 2: round x and W to fp16 (RN) ----------------
__global__ __launch_bounds__(256) void round_kernel(const float4* __restrict__ x,
                                                    const float4* __restrict__ W) {
    const size_t nx = (size_t)T_TOK * DDIM / 4;
    const size_t nw = (size_t)NOUT * DDIM / 4;
    __half2* ox = (__half2*)g_xh;
    __half2* ow = (__half2*)g_wh;
    size_t stride = (size_t)gridDim.x * blockDim.x;
    for (size_t i = (size_t)blockIdx.x * blockDim.x + threadIdx.x; i < nx + nw; i += stride) {
        float4 v;
        __half2* dst;
        if (i < nx) { v = x[i]; dst = ox + 2 * i; }
        else        { v = W[i - nx]; dst = ow + 2 * (i - nx); }
        dst[0] = __floats2half2_rn(v.x, v.y);
        dst[1] = __floats2half2_rn(v.z, v.w);
    }
}

// ---------------- kernel 3: xa[t, j] = sum_d x[t,d] * A[l, d, j] ----------------
__global__ __launch_bounds__(512) void xa_kernel(const float* __restrict__ x,
                                                 const float* __restrict__ A) {
    __shared__ float As[128 * 32];
    int l = blockIdx.y;
    int d0 = blockIdx.x * 128;
    int tid = threadIdx.x;
    int lane = tid & 31, w = tid >> 5;

    size_t abase = ((size_t)l * DDIM + d0) * 32;
    for (int i = tid; i < 128 * 32; i += 512) As[i] = A[abase + i];
    __syncthreads();

    int pbeg = g_start[l], pend = g_start[l + 1];
    for (int p = pbeg + w; p < pend; p += 16) {
        int t = g_tok[p];
        float xv[4];
#pragma unroll
        for (int s = 0; s < 4; ++s)
            xv[s] = x[(size_t)t * DDIM + d0 + s * 32 + lane];
        float acc = 0.0f;
#pragma unroll
        for (int s = 0; s < 4; ++s) {
#pragma unroll
            for (int i = 0; i < 32; ++i) {
                float xb = __shfl_sync(0xffffffffu, xv[s], i);
                acc += xb * As[(s * 32 + i) * 32 + lane];
            }
        }
        atomicAdd(&g_xa[t * 32 + lane], acc);
    }
}

// ---------------- kernel 4: delta -> out (full init), B in regs, 4-way z-split
__global__ __launch_bounds__(256) void delta_kernel(const float* __restrict__ B,
                                                    float* __restrict__ out) {
    int l = blockIdx.y;
    int n0 = blockIdx.x * 512;
    int half = (n0 >= HALF_B) ? 1 : 0;
    int tid = threadIdx.x;
    int c0 = n0 + 2 * tid;

    int pbeg = g_start[l], pend = g_start[l + 1];
    int len = pend - pbeg;
    int per = (len + 3) >> 2;
    int s = pbeg + blockIdx.z * per;
    int e = s + per;
    if (e > pend) e = pend;
    if (s >= e) return;

    float2 Breg[16];
#pragma unroll
    for (int r = 0; r < 16; ++r)
        Breg[r] = *(const float2*)(B + ((size_t)l * 16 + r) * NOUT + c0);

    const float4* xa4base = (const float4*)(g_xa) + half * 4;

    for (int p = s; p < e; ++p) {
        int t = g_tok[p];
        float4 x0 = __ldg(xa4base + t * 8 + 0);
        float4 x1 = __ldg(xa4base + t * 8 + 1);
        float4 x2 = __ldg(xa4base + t * 8 + 2);
        float4 x3 = __ldg(xa4base + t * 8 + 3);
        float xs[16] = {x0.x, x0.y, x0.z, x0.w, x1.x, x1.y, x1.z, x1.w,
                        x2.x, x2.y, x2.z, x2.w, x3.x, x3.y, x3.z, x3.w};
        float2 acc = make_float2(0.0f, 0.0f);
#pragma unroll
        for (int r = 0; r < 16; ++r) {
            acc.x += xs[r] * Breg[r].x;
            acc.y += xs[r] * Breg[r].y;
        }
        *(float2*)(out + (size_t)t * NOUT + c0) = acc;
    }
}

// ---------------- kernel 5: main GEMM (fp16 mma.sync m16n8k16) ---------------
#define BM 128
#define BN 128
#define BK 32
#define PADH 40                         // halfs per smem row: 80 B stride (16B-aligned, conflict-free)
#define STAGES 3
#define STAGE_HALFS ((BM + BN) * PADH)  // 10240 halfs
#define STAGE_BYTES (STAGE_HALFS * 2)   // 20480 B
#define SMEM_GEMM (STAGES * STAGE_BYTES)

__device__ __forceinline__ void cpa16(uint32_t s, const void* g) {
    asm volatile("cp.async.cg.shared.global [%0], [%1], 16;\n" :: "r"(s), "l"(g));
}

__global__ __launch_bounds__(256, 2) void gemm_kernel(float* __restrict__ out) {
    extern __shared__ __half smem[];

    int tid = threadIdx.x;
    int lane = tid & 31;
    int warp = tid >> 5;
    int warpM = warp & 3;    // 4 warps in M  -> 32 rows each
    int warpN = warp >> 2;   // 2 warps in N  -> 64 cols each
    int grp = lane >> 2;     // 0..7
    int qid = lane & 3;      // 0..3

    int bm = blockIdx.x;     // 0..15
    int bn = blockIdx.y;     // 0..87

    const __half* gA = g_xh + (size_t)(bm * BM) * DDIM;
    const __half* gB = g_wh + (size_t)(bn * BN) * DDIM;

    // cp.async mapping: 256 rows x 4 segs of 16B (8 halfs); 4 chunks/thread
    int rbase = tid >> 2;    // 0..63
    int seg = tid & 3;       // 0..3

    uint32_t sBase = (uint32_t)__cvta_generic_to_shared(smem);

    float c[2][8][4];
#pragma unroll
    for (int mt = 0; mt < 2; ++mt)
#pragma unroll
        for (int nt = 0; nt < 8; ++nt)
#pragma unroll
            for (int i = 0; i < 4; ++i) c[mt][nt][i] = 0.0f;

    auto loadTiles = [&](int buf, int k0) {
        uint32_t soff = sBase + (uint32_t)buf * STAGE_BYTES;
#pragma unroll
        for (int i = 0; i < 4; ++i) {
            int row = rbase + i * 64;          // 0..255 (A rows 0-127, B rows 128-255)
            const __half* src = (row < BM)
                ? (gA + (size_t)row * DDIM + k0 + seg * 8)
                : (gB + (size_t)(row - BM) * DDIM + k0 + seg * 8);
            cpa16(soff + (uint32_t)(row * PADH * 2 + seg * 16), src);
        }
        asm volatile("cp.async.commit_group;\n");
    };

    auto compute = [&](uint32_t base) {   // base = sBase + buf*STAGE_BYTES
        uint32_t aRowOff = (uint32_t)((warpM * 32 + grp) * PADH * 2);
        uint32_t bRowOff = (uint32_t)(BM * PADH * 2 + (warpN * 64 + grp) * PADH * 2);
#pragma unroll
        for (int ks = 0; ks < 2; ++ks) {     // two k16 steps cover BK=32
            uint32_t kb = (uint32_t)(ks * 32 + qid * 4);   // bytes: k offset
            uint32_t a[2][4], b[8][2];
#pragma unroll
            for (int mt = 0; mt < 2; ++mt) {
                uint32_t r0 = base + aRowOff + (uint32_t)(mt * 16 * PADH * 2) + kb;
                uint32_t r1 = r0 + (uint32_t)(8 * PADH * 2);
                asm volatile("ld.shared.b32 %0, [%1];" : "=r"(a[mt][0]) : "r"(r0));
                asm volatile("ld.shared.b32 %0, [%1];" : "=r"(a[mt][1]) : "r"(r1));
                asm volatile("ld.shared.b32 %0, [%1];" : "=r"(a[mt][2]) : "r"(r0 + 16));
                asm volatile("ld.shared.b32 %0, [%1];" : "=r"(a[mt][3]) : "r"(r1 + 16));
            }
#pragma unroll
            for (int nt = 0; nt < 8; ++nt) {
                uint32_t rb = base + bRowOff + (uint32_t)(nt * 8 * PADH * 2) + kb;
                asm volatile("ld.shared.b32 %0, [%1];" : "=r"(b[nt][0]) : "r"(rb));
                asm volatile("ld.shared.b32 %0, [%1];" : "=r"(b[nt][1]) : "r"(rb + 16));
            }
#pragma unroll
            for (int mt = 0; mt < 2; ++mt) {
#pragma unroll
                for (int nt = 0; nt < 8; ++nt) {
                    asm volatile(
                        "mma.sync.aligned.m16n8k16.row.col.f32.f16.f16.f32 "
                        "{%0,%1,%2,%3}, {%4,%5,%6,%7}, {%8,%9}, {%0,%1,%2,%3};\n"
                        : "+f"(c[mt][nt][0]), "+f"(c[mt][nt][1]),
                          "+f"(c[mt][nt][2]), "+f"(c[mt][nt][3])
                        : "r"(a[mt][0]), "r"(a[mt][1]), "r"(a[mt][2]), "r"(a[mt][3]),
                          "r"(b[nt][0]), "r"(b[nt][1]));
                }
            }
        }
    };

    loadTiles(0, 0);
    loadTiles(1, BK);

    const int NITER = DDIM / BK;   // 64
#pragma unroll 1
    for (int it = 0; it < NITER - 4; it += 3) {
#pragma unroll
        for (int u = 0; u < 3; ++u) {
            asm volatile("cp.async.wait_group 1;\n");
            __syncthreads();
            loadTiles((u + 2) % STAGES, (it + u + 2) * BK);
            compute(sBase + (uint32_t)u * STAGE_BYTES);
        }
    }
    // tail: it = 60..63 (60 % 3 == 0)
#pragma unroll
    for (int u = 0; u < 4; ++u) {
        int it = 60 + u;
        if (it < NITER - 1) {
            asm volatile("cp.async.wait_group 1;\n");
        } else {
            asm volatile("cp.async.wait_group 0;\n");
        }
        __syncthreads();
        if (it + 2 < NITER)
            loadTiles((u + 2) % STAGES, (it + 2) * BK);
        compute(sBase + (uint32_t)((u % STAGES) * STAGE_BYTES));
    }

    // epilogue: out += acc (out already holds delta)
#pragma unroll
    for (int mt = 0; mt < 2; ++mt) {
#pragma unroll
        for (int nt = 0; nt < 8; ++nt) {
            int r = bm * BM + warpM * 32 + mt * 16 + grp;
            int col = bn * BN + warpN * 64 + nt * 8 + qid * 2;
            size_t o = (size_t)r * NOUT + col;
            float2* p0 = (float2*)(out + o);
            float2 v0 = *p0;
            v0.x += c[mt][nt][0];
            v0.y += c[mt][nt][1];
            *p0 = v0;
            float2* p1 = (float2*)(out + o + (size_t)8 * NOUT);
            float2 v1 = *p1;
            v1.x += c[mt][nt][2];
            v1.y += c[mt][nt][3];
            *p1 = v1;
        }
    }
}

// ---------------- launch ----------------
extern "C" void kernel_launch(void* const* d_in, const int* in_sizes, int n_in,
                              void* d_out, int out_size) {
    const float* x = (const float*)d_in[0];
    const float* W = (const float*)d_in[1];
    const float* A = (const float*)d_in[2];
    const float* B = (const float*)d_in[3];
    const void*  idx = d_in[4];
    float* out = (float*)d_out;

    (void)in_sizes; (void)n_in; (void)out_size;

    cudaFuncSetAttribute(gemm_kernel, cudaFuncAttributeMaxDynamicSharedMemorySize, SMEM_GEMM);

    sort_kernel<<<1, 1024>>>(idx);
    round_kernel<<<2048, 256>>>((const float4*)x, (const float4*)W);
    xa_kernel<<<dim3(16, 16), 512>>>(x, A);
    delta_kernel<<<dim3(22, 16, 4), 256>>>(B, out);
    gemm_kernel<<<dim3(16, 88), 256, SMEM_GEMM>>>(out);
}

// round 12
// speedup vs baseline: 2.1292x; 1.6078x over previous
#include <cuda_runtime.h>
#include <cuda_fp16.h>
#include <cstdint>

#define T_TOK 2048
#define DDIM  2048
#define NOUT  11264
#define LEXP  16
#define HALF_B 5632

// ---------------- scratch (device globals: allocation-free) ----------------
__device__ __align__(16) __half g_xh[(size_t)T_TOK * DDIM];  // fp16-rounded x
__device__ __align__(16) __half g_wh[(size_t)NOUT * DDIM];   // fp16-rounded W
__device__ float g_xa[T_TOK * 32];                           // xa = x . A[l]
__device__ int   g_tok[T_TOK];                               // tokens sorted by expert
__device__ int   g_start[LEXP + 1];                          // expert segment starts

// ---------------- kernel 1: bucket tokens by expert + zero xa ----------------
__global__ __launch_bounds__(1024) void sort_kernel(const void* idx_raw) {
    __shared__ int cnt[LEXP];
    __shared__ int base[LEXP];
    __shared__ int is64;
    int tid = threadIdx.x;
    if (tid < LEXP) cnt[tid] = 0;
    if (tid == 0) is64 = 1;
    __syncthreads();

    // sniff int32 vs int64: if int64 (values in [0,16)), every odd 32-bit word is 0
    const int* a32 = (const int*)idx_raw;
    for (int j = tid; j < 1024; j += blockDim.x)
        if (a32[2 * j + 1] != 0) is64 = 0;   // benign race
    __syncthreads();
    const long long* a64 = (const long long*)idx_raw;
    int use64 = is64;

    for (int t = tid; t < T_TOK; t += blockDim.x) {
        int l = use64 ? (int)a64[t] : a32[t];
        atomicAdd(&cnt[l], 1);
    }
    __syncthreads();
    if (tid == 0) {
        int s = 0;
        for (int l = 0; l < LEXP; ++l) { base[l] = s; g_start[l] = s; s += cnt[l]; }
        g_start[LEXP] = s;
    }
    __syncthreads();
    for (int t = tid; t < T_TOK; t += blockDim.x) {
        int l = use64 ? (int)a64[t] : a32[t];
        int p = atomicAdd(&base[l], 1);
        g_tok[p] = t;
    }
    for (int i = tid; i < T_TOK * 32; i += blockDim.x) g_xa[i] = 0.0f;
}

// ---------------- kernel 2: round x and W to fp16 (RN) ----------------
__global__ __launch_bounds__(256) void round_kernel(const float4* __restrict__ x,
                                                    const float4* __restrict__ W) {
    const size_t nx = (size_t)T_TOK * DDIM / 4;
    const size_t nw = (size_t)NOUT * DDIM / 4;
    __half2* ox = (__half2*)g_xh;
    __half2* ow = (__half2*)g_wh;
    size_t stride = (size_t)gridDim.x * blockDim.x;
    for (size_t i = (size_t)blockIdx.x * blockDim.x + threadIdx.x; i < nx + nw; i += stride) {
        float4 v;
        __half2* dst;
        if (i < nx) { v = x[i]; dst = ox + 2 * i; }
        else        { v = W[i - nx]; dst = ow + 2 * (i - nx); }
        dst[0] = __floats2half2_rn(v.x, v.y);
        dst[1] = __floats2half2_rn(v.z, v.w);
    }
}

// ---------------- kernel 3: xa[t, j] = sum_d x[t,d] * A[l, d, j] ----------------
__global__ __launch_bounds__(512) void xa_kernel(const float* __restrict__ x,
                                                 const float* __restrict__ A) {
    __shared__ float As[128 * 32];
    int l = blockIdx.y;
    int d0 = blockIdx.x * 128;
    int tid = threadIdx.x;
    int lane = tid & 31, w = tid >> 5;

    size_t abase = ((size_t)l * DDIM + d0) * 32;
    for (int i = tid; i < 128 * 32; i += 512) As[i] = A[abase + i];
    __syncthreads();

    int pbeg = g_start[l], pend = g_start[l + 1];
    for (int p = pbeg + w; p < pend; p += 16) {
        int t = g_tok[p];
        float xv[4];
#pragma unroll
        for (int s = 0; s < 4; ++s)
            xv[s] = x[(size_t)t * DDIM + d0 + s * 32 + lane];
        float acc = 0.0f;
#pragma unroll
        for (int s = 0; s < 4; ++s) {
#pragma unroll
            for (int i = 0; i < 32; ++i) {
                float xb = __shfl_sync(0xffffffffu, xv[s], i);
                acc += xb * As[(s * 32 + i) * 32 + lane];
            }
        }
        atomicAdd(&g_xa[t * 32 + lane], acc);
    }
}

// ---------------- kernel 4: delta -> out (full init), B in regs, 4-way z-split
__global__ __launch_bounds__(256) void delta_kernel(const float* __restrict__ B,
                                                    float* __restrict__ out) {
    int l = blockIdx.y;
    int n0 = blockIdx.x * 512;
    int half = (n0 >= HALF_B) ? 1 : 0;
    int tid = threadIdx.x;
    int c0 = n0 + 2 * tid;

    int pbeg = g_start[l], pend = g_start[l + 1];
    int len = pend - pbeg;
    int per = (len + 3) >> 2;
    int s = pbeg + blockIdx.z * per;
    int e = s + per;
    if (e > pend) e = pend;
    if (s >= e) return;

    float2 Breg[16];
#pragma unroll
    for (int r = 0; r < 16; ++r)
        Breg[r] = *(const float2*)(B + ((size_t)l * 16 + r) * NOUT + c0);

    const float4* xa4base = (const float4*)(g_xa) + half * 4;

    for (int p = s; p < e; ++p) {
        int t = g_tok[p];
        float4 x0 = __ldg(xa4base + t * 8 + 0);
        float4 x1 = __ldg(xa4base + t * 8 + 1);
        float4 x2 = __ldg(xa4base + t * 8 + 2);
        float4 x3 = __ldg(xa4base + t * 8 + 3);
        float xs[16] = {x0.x, x0.y, x0.z, x0.w, x1.x, x1.y, x1.z, x1.w,
                        x2.x, x2.y, x2.z, x2.w, x3.x, x3.y, x3.z, x3.w};
        float2 acc = make_float2(0.0f, 0.0f);
#pragma unroll
        for (int r = 0; r < 16; ++r) {
            acc.x += xs[r] * Breg[r].x;
            acc.y += xs[r] * Breg[r].y;
        }
        *(float2*)(out + (size_t)t * NOUT + c0) = acc;
    }
}

// ------- kernel 5: main GEMM (fp16 mma.sync m16n8k16, BK=64, 2 stages) -------
#define BM 128
#define BN 128
#define BK 64
#define PADH 72                         // halfs per smem row: 144 B stride (16B-aligned, conflict-free)
#define STAGE_BYTES ((BM + BN) * PADH * 2)   // 36864 B
#define SMEM_GEMM (2 * STAGE_BYTES)          // 73728 B -> 2 CTAs/SM

__device__ __forceinline__ void cpa16(uint32_t s, const void* g) {
    asm volatile("cp.async.cg.shared.global [%0], [%1], 16;\n" :: "r"(s), "l"(g));
}

__global__ __launch_bounds__(256, 2) void gemm_kernel(float* __restrict__ out) {
    extern __shared__ __half smem[];

    int tid = threadIdx.x;
    int lane = tid & 31;
    int warp = tid >> 5;
    int warpM = warp & 3;    // 4 warps in M  -> 32 rows each
    int warpN = warp >> 2;   // 2 warps in N  -> 64 cols each
    int grp = lane >> 2;     // 0..7
    int qid = lane & 3;      // 0..3

    int bm = blockIdx.x;     // 0..15
    int bn = blockIdx.y;     // 0..87

    const __half* gA = g_xh + (size_t)(bm * BM) * DDIM;
    const __half* gB = g_wh + (size_t)(bn * BN) * DDIM;

    // cp.async mapping: 256 rows x 8 segs of 16B (128 B per row); 8 chunks/thread
    int rbase = tid >> 3;    // 0..31
    int seg = tid & 7;       // 0..7

    uint32_t sBase = (uint32_t)__cvta_generic_to_shared(smem);

    float c[2][8][4];
#pragma unroll
    for (int mt = 0; mt < 2; ++mt)
#pragma unroll
        for (int nt = 0; nt < 8; ++nt)
#pragma unroll
            for (int i = 0; i < 4; ++i) c[mt][nt][i] = 0.0f;

    auto loadTiles = [&](int buf, int k0) {
        uint32_t soff = sBase + (uint32_t)buf * STAGE_BYTES;
#pragma unroll
        for (int i = 0; i < 8; ++i) {
            int row = rbase + i * 32;          // 0..255 (A rows 0-127, B rows 128-255)
            const __half* src = (row < BM)
                ? (gA + (size_t)row * DDIM + k0 + seg * 8)
                : (gB + (size_t)(row - BM) * DDIM + k0 + seg * 8);
            cpa16(soff + (uint32_t)(row * PADH * 2 + seg * 16), src);
        }
        asm volatile("cp.async.commit_group;\n");
    };

    auto compute = [&](uint32_t base) {   // base = sBase + buf*STAGE_BYTES
        uint32_t aRowOff = (uint32_t)((warpM * 32 + grp) * PADH * 2);
        uint32_t bRowOff = (uint32_t)(BM * PADH * 2 + (warpN * 64 + grp) * PADH * 2);
#pragma unroll
        for (int ks = 0; ks < 4; ++ks) {     // four k16 steps cover BK=64
            uint32_t kb = (uint32_t)(ks * 32 + qid * 4);   // byte offset in row
            uint32_t a[2][4], b[8][2];
#pragma unroll
            for (int mt = 0; mt < 2; ++mt) {
                uint32_t r0 = base + aRowOff + (uint32_t)(mt * 16 * PADH * 2) + kb;
                uint32_t r1 = r0 + (uint32_t)(8 * PADH * 2);
                asm volatile("ld.shared.b32 %0, [%1];" : "=r"(a[mt][0]) : "r"(r0));
                asm volatile("ld.shared.b32 %0, [%1];" : "=r"(a[mt][1]) : "r"(r1));
                asm volatile("ld.shared.b32 %0, [%1];" : "=r"(a[mt][2]) : "r"(r0 + 16));
                asm volatile("ld.shared.b32 %0, [%1];" : "=r"(a[mt][3]) : "r"(r1 + 16));
            }
#pragma unroll
            for (int nt = 0; nt < 8; ++nt) {
                uint32_t rb = base + bRowOff + (uint32_t)(nt * 8 * PADH * 2) + kb;
                asm volatile("ld.shared.b32 %0, [%1];" : "=r"(b[nt][0]) : "r"(rb));
                asm volatile("ld.shared.b32 %0, [%1];" : "=r"(b[nt][1]) : "r"(rb + 16));
            }
#pragma unroll
            for (int mt = 0; mt < 2; ++mt) {
#pragma unroll
                for (int nt = 0; nt < 8; ++nt) {
                    asm volatile(
                        "mma.sync.aligned.m16n8k16.row.col.f32.f16.f16.f32 "
                        "{%0,%1,%2,%3}, {%4,%5,%6,%7}, {%8,%9}, {%0,%1,%2,%3};\n"
                        : "+f"(c[mt][nt][0]), "+f"(c[mt][nt][1]),
                          "+f"(c[mt][nt][2]), "+f"(c[mt][nt][3])
                        : "r"(a[mt][0]), "r"(a[mt][1]), "r"(a[mt][2]), "r"(a[mt][3]),
                          "r"(b[nt][0]), "r"(b[nt][1]));
                }
            }
        }
    };

    loadTiles(0, 0);

    const int NITER = DDIM / BK;   // 32
    // double buffer, unrolled x2 so stage bases are compile-time constants.
#pragma unroll 1
    for (int it = 0; it < NITER; it += 2) {
        // --- iter it (buf 0) ---
        asm volatile("cp.async.wait_group 0;\n");
        __syncthreads();
        loadTiles(1, (it + 1) * BK);
        compute(sBase);
        // --- iter it+1 (buf 1) ---
        asm volatile("cp.async.wait_group 0;\n");
        __syncthreads();
        if (it + 2 < NITER)
            loadTiles(0, (it + 2) * BK);
        compute(sBase + STAGE_BYTES);
    }

    // epilogue: out += acc (out already holds delta)
#pragma unroll
    for (int mt = 0; mt < 2; ++mt) {
#pragma unroll
        for (int nt = 0; nt < 8; ++nt) {
            int r = bm * BM + warpM * 32 + mt * 16 + grp;
            int col = bn * BN + warpN * 64 + nt * 8 + qid * 2;
            size_t o = (size_t)r * NOUT + col;
            float2* p0 = (float2*)(out + o);
            float2 v0 = *p0;
            v0.x += c[mt][nt][0];
            v0.y += c[mt][nt][1];
            *p0 = v0;
            float2* p1 = (float2*)(out + o + (size_t)8 * NOUT);
            float2 v1 = *p1;
            v1.x += c[mt][nt][2];
            v1.y += c[mt][nt][3];
            *p1 = v1;
        }
    }
}

// ---------------- launch ----------------
extern "C" void kernel_launch(void* const* d_in, const int* in_sizes, int n_in,
                              void* d_out, int out_size) {
    const float* x = (const float*)d_in[0];
    const float* W = (const float*)d_in[1];
    const float* A = (const float*)d_in[2];
    const float* B = (const float*)d_in[3];
    const void*  idx = d_in[4];
    float* out = (float*)d_out;

    (void)in_sizes; (void)n_in; (void)out_size;

    cudaFuncSetAttribute(gemm_kernel, cudaFuncAttributeMaxDynamicSharedMemorySize, SMEM_GEMM);

    sort_kernel<<<1, 1024>>>(idx);
    round_kernel<<<2048, 256>>>((const float4*)x, (const float4*)W);
    xa_kernel<<<dim3(16, 16), 512>>>(x, A);
    delta_kernel<<<dim3(22, 16, 4), 256>>>(B, out);
    gemm_kernel<<<dim3(16, 88), 256, SMEM_GEMM>>>(out);
}